// round 5
// baseline (speedup 1.0000x reference)
#include <cuda_runtime.h>
#include <math.h>
#include <float.h>

#define BS    4096
#define LSEQ  200
#define KCAPS 4
#define VOCAB 100000
#define HPS   65    // k_es Esm stride
#define TPS   209   // hisPT u64 row stride: 209*8 mod 128 == 8 -> conflict-free

typedef unsigned long long u64;

// ---- packed fp32x2 helpers (Blackwell FFMA2 path) ----
__device__ __forceinline__ u64 pack2(float x, float y) {
    u64 r; asm("mov.b64 %0, {%1, %2};" : "=l"(r) : "f"(x), "f"(y)); return r;
}
__device__ __forceinline__ u64 pack_dup(float x) {
    u64 r; asm("mov.b64 %0, {%1, %1};" : "=l"(r) : "f"(x)); return r;
}
__device__ __forceinline__ void unpack2(u64 v, float& x, float& y) {
    asm("mov.b64 {%0, %1}, %2;" : "=f"(x), "=f"(y) : "l"(v));
}
__device__ __forceinline__ void ffma2(u64& d, u64 a, u64 b) {
    asm("fma.rn.f32x2 %0, %1, %2, %0;" : "+l"(d) : "l"(a), "l"(b));
}
__device__ __forceinline__ u64 fadd2(u64 a, u64 b) {
    u64 r; asm("add.rn.f32x2 %0, %1, %2;" : "=l"(r) : "l"(a), "l"(b)); return r;
}

// Scratch (allocation-free: device globals)
__device__ float g_ES[VOCAB * 64];            // 25.6 MB: E @ S, row 0 zeroed
__device__ float g_caps[BS * KCAPS * 64];     // 4 MB: routing output

// ---------------------------------------------------------------------------
// Kernel 1: ES = E @ S, packed FFMA2. 128 rows/CTA, thread tile 8x(2 pairs).
// ---------------------------------------------------------------------------
__global__ __launch_bounds__(256) void k_es(const float* __restrict__ E,
                                            const float* __restrict__ S) {
    extern __shared__ float sm[];
    float* Ssm = sm;                 // 64*64
    float* Esm = sm + 4096;          // 128*65
    const int tid = threadIdx.x;
    const int v0 = blockIdx.x * 128;

    for (int i = tid; i < 1024; i += 256)
        ((float4*)Ssm)[i] = ((const float4*)S)[i];
    for (int i = tid; i < 2048; i += 256) {       // 128 rows * 16 float4
        int r = i >> 4, e4 = i & 15;
        int v = v0 + r;
        float4 val = make_float4(0.f, 0.f, 0.f, 0.f);
        if (v < VOCAB) val = *(const float4*)&E[(size_t)v * 64 + e4 * 4];
        float* p = &Esm[r * HPS + e4 * 4];
        p[0] = val.x; p[1] = val.y; p[2] = val.z; p[3] = val.w;
    }
    __syncthreads();

    const int vg = tid >> 4;   // 16 groups x 8 rows
    const int dg = tid & 15;   // 16 groups x 4 cols (2 pairs)
    u64 acc[8][2];
#pragma unroll
    for (int r = 0; r < 8; r++) { acc[r][0] = 0ull; acc[r][1] = 0ull; }

#pragma unroll 4
    for (int e = 0; e < 64; e++) {
        ulonglong2 sv = *(ulonglong2*)&Ssm[e * 64 + dg * 4];
        u64 ed[8];
#pragma unroll
        for (int r = 0; r < 8; r++) ed[r] = pack_dup(Esm[(vg * 8 + r) * HPS + e]);
#pragma unroll
        for (int r = 0; r < 8; r++) {
            ffma2(acc[r][0], ed[r], sv.x);
            ffma2(acc[r][1], ed[r], sv.y);
        }
    }

#pragma unroll
    for (int r = 0; r < 8; r++) {
        int v = v0 + vg * 8 + r;
        if (v >= VOCAB) continue;
        float4 o;
        unpack2(acc[r][0], o.x, o.y);
        unpack2(acc[r][1], o.z, o.w);
        if (v == 0) o = make_float4(0.f, 0.f, 0.f, 0.f);   // padding_idx row
        *(float4*)&g_ES[(size_t)v * 64 + dg * 4] = o;
    }
}

// ---------------------------------------------------------------------------
// Kernel 2: routing. One CTA/batch, 256 threads.
// hisP: register copy (caps loop) + transposed smem copy [dp][l] (B-update).
// ---------------------------------------------------------------------------
__global__ __launch_bounds__(256) void k_route(const int* __restrict__ his,
                                               const float* __restrict__ B0) {
    extern __shared__ u64 smu[];
    u64*   part2 = smu;                    // [8 lc][k*32+dp]  1024 u64
    u64*   WkT2  = part2 + 1024;           // [l][k] dup-packed exp  800 u64
    u64*   capsB = WkT2 + 800;             // [dp][k] packed caps  128 u64 (16B aligned)
    u64*   hisPT = capsB + 128;            // [dp][l] 32*209 u64
    float* Bk    = (float*)(hisPT + 32 * TPS);  // [k][l] 800
    float* invs  = Bk + 4 * LSEQ;          // 4
    int*   idx   = (int*)(invs + 4);       // 200

    const int tid  = threadIdx.x;
    const int b    = blockIdx.x;
    const int lane = tid & 31;
    const int w    = tid >> 5;
    const int l0   = w * 25;
    const float DROPV = -2147483648.0f;

    for (int l = tid; l < LSEQ; l += 256) idx[l] = his[b * LSEQ + l];
    for (int t = tid; t < 4 * LSEQ; t += 256) Bk[t] = B0[t];
    __syncthreads();

    // Gather this thread's hisP slice into registers (coalesced LDG.64),
    // mirror into transposed smem for the B-update.
    u64 h2[25];
#pragma unroll
    for (int i = 0; i < 25; i++) {
        int v = idx[l0 + i];
        h2[i] = ((const u64*)g_ES)[(size_t)v * 32 + lane];
        hisPT[lane * TPS + l0 + i] = h2[i];
    }

    for (int it = 0; it < 3; it++) {
        // ---- masked softmax over L, warps 0..3 handle k = w ----
        if (w < 4) {
            float m = -FLT_MAX;
            for (int l = lane; l < LSEQ; l += 32) {
                float v = (idx[l] != 0) ? Bk[w * LSEQ + l] : DROPV;
                m = fmaxf(m, v);
            }
#pragma unroll
            for (int o = 16; o > 0; o >>= 1) m = fmaxf(m, __shfl_xor_sync(0xffffffffu, m, o));
            float s = 0.f;
            for (int l = lane; l < LSEQ; l += 32) {
                float v = (idx[l] != 0) ? Bk[w * LSEQ + l] : DROPV;
                float e = __expf(v - m);
                WkT2[l * 4 + w] = pack_dup(e);
                s += e;
            }
#pragma unroll
            for (int o = 16; o > 0; o >>= 1) s += __shfl_xor_sync(0xffffffffu, s, o);
            if (lane == 0) invs[w] = 1.f / s;
        }
        __syncthreads();

        // ---- caps partials: register h, broadcast W ----
        {
            u64 a0 = 0ull, a1 = 0ull, a2 = 0ull, a3 = 0ull;
#pragma unroll
            for (int i = 0; i < 25; i++) {
                const int l = l0 + i;
                ulonglong2 w01 = *(ulonglong2*)&WkT2[l * 4];       // broadcast
                ulonglong2 w23 = *(ulonglong2*)&WkT2[l * 4 + 2];
                ffma2(a0, h2[i], w01.x);
                ffma2(a1, h2[i], w01.y);
                ffma2(a2, h2[i], w23.x);
                ffma2(a3, h2[i], w23.y);
            }
            part2[w * 128 +  0 + lane] = a0;
            part2[w * 128 + 32 + lane] = a1;
            part2[w * 128 + 64 + lane] = a2;
            part2[w * 128 + 96 + lane] = a3;
        }
        __syncthreads();

        // ---- reduce partials (tid<128: warp = k, lane = dp), squash ----
        if (tid < 128) {
            const int k = tid >> 5;
            u64 c2 = part2[tid];
#pragma unroll
            for (int lc = 1; lc < 8; lc++) c2 = fadd2(c2, part2[lc * 128 + tid]);
            float cx, cy;
            unpack2(c2, cx, cy);
            float inv = invs[k];
            cx *= inv; cy *= inv;
            float sq = cx * cx + cy * cy;
#pragma unroll
            for (int o = 16; o > 0; o >>= 1) sq += __shfl_xor_sync(0xffffffffu, sq, o);
            float n2 = sq;
            float n  = sqrtf(n2);
            float scale = n2 / ((1.f + n2) * n + 1e-9f);
            cx *= scale; cy *= scale;
            if (it == 2) {
                *(float2*)&g_caps[b * 256 + 2 * tid] = make_float2(cx, cy);
            } else {
                capsB[lane * 4 + k] = pack2(cx, cy);   // [dp][k]
            }
        }
        if (it == 2) break;
        __syncthreads();

        // ---- B[k][l] += dot(caps[k], hisP[l]) : thread-per-l, transposed h ----
        if (tid < LSEQ) {
            const int l = tid;
            u64 s0 = 0ull, s1 = 0ull, s2 = 0ull, s3 = 0ull;
#pragma unroll 8
            for (int dp = 0; dp < 32; dp++) {
                u64 h = hisPT[dp * TPS + l];                       // stride-1 over l
                ulonglong2 c01 = *(ulonglong2*)&capsB[dp * 4];     // broadcast
                ulonglong2 c23 = *(ulonglong2*)&capsB[dp * 4 + 2];
                ffma2(s0, h, c01.x);
                ffma2(s1, h, c01.y);
                ffma2(s2, h, c23.x);
                ffma2(s3, h, c23.y);
            }
            float x, y;
            unpack2(s0, x, y); Bk[0 * LSEQ + l] += x + y;
            unpack2(s1, x, y); Bk[1 * LSEQ + l] += x + y;
            unpack2(s2, x, y); Bk[2 * LSEQ + l] += x + y;
            unpack2(s3, x, y); Bk[3 * LSEQ + l] += x + y;
        }
        __syncthreads();
    }
}

// ---------------------------------------------------------------------------
// Kernel 3: batched MLP, f-chunked (4x64), packed FFMA2 in both GEMMs.
// ---------------------------------------------------------------------------
__global__ __launch_bounds__(256) void k_mlp(const float* __restrict__ W1,
                                             const float* __restrict__ b1,
                                             const float* __restrict__ W2,
                                             const float* __restrict__ b2,
                                             float* __restrict__ out) {
    extern __shared__ float sm[];
    float* W1c = sm;                 // 64*64 (e x f-chunk)
    float* W2c = W1c + 4096;         // 64*64 (f-chunk x d)
    float* cs  = W2c + 4096;         // 64*65 caps rows (padded)
    float* hs  = cs + 64 * 65;       // 64*68 h chunk (padded)
    float* b1s = hs + 64 * 68;       // 256
    float* b2s = b1s + 256;          // 64
    const int tid  = threadIdx.x;
    const int row0 = blockIdx.x * 64;

    for (int i = tid; i < 4096; i += 256) {
        int r = i >> 6, e = i & 63;
        cs[r * 65 + e] = g_caps[row0 * 64 + i];
    }
    if (tid < 256) b1s[tid] = b1[tid];
    if (tid < 64)  b2s[tid] = b2[tid];

    const int rq = tid >> 4;   // 16 groups x 4 rows
    const int dq = tid & 15;   // 16 groups x 4 cols (2 pairs)
    u64 acc2[4][2];
#pragma unroll
    for (int i = 0; i < 4; i++) { acc2[i][0] = 0ull; acc2[i][1] = 0ull; }

    for (int ch = 0; ch < 4; ch++) {
        const int f0 = ch * 64;
        __syncthreads();
        for (int i4 = tid; i4 < 1024; i4 += 256) {
            int e = i4 >> 4, j4 = i4 & 15;
            ((float4*)W1c)[i4] = *(const float4*)&W1[e * 256 + f0 + j4 * 4];
        }
        for (int i4 = tid; i4 < 1024; i4 += 256)
            ((float4*)W2c)[i4] = ((const float4*)&W2[f0 * 64])[i4];
        __syncthreads();

        // GEMM1: h[64][64] = cs @ W1c (+b1, relu)
        {
            u64 acc1[4][2];
#pragma unroll
            for (int i = 0; i < 4; i++) { acc1[i][0] = 0ull; acc1[i][1] = 0ull; }
#pragma unroll 4
            for (int e = 0; e < 64; e++) {
                u64 cd[4];
#pragma unroll
                for (int i = 0; i < 4; i++) cd[i] = pack_dup(cs[(rq * 4 + i) * 65 + e]);
                ulonglong2 wv = *(ulonglong2*)&W1c[e * 64 + dq * 4];
#pragma unroll
                for (int i = 0; i < 4; i++) {
                    ffma2(acc1[i][0], cd[i], wv.x);
                    ffma2(acc1[i][1], cd[i], wv.y);
                }
            }
            float4 bb = *(float4*)&b1s[f0 + dq * 4];
#pragma unroll
            for (int i = 0; i < 4; i++) {
                float4 h; float x, y;
                unpack2(acc1[i][0], x, y); h.x = fmaxf(x + bb.x, 0.f); h.y = fmaxf(y + bb.y, 0.f);
                unpack2(acc1[i][1], x, y); h.z = fmaxf(x + bb.z, 0.f); h.w = fmaxf(y + bb.w, 0.f);
                *(float4*)&hs[(rq * 4 + i) * 68 + dq * 4] = h;
            }
        }
        __syncthreads();

        // GEMM2 accumulate: out[64][64] += h_chunk @ W2c
#pragma unroll 4
        for (int f = 0; f < 64; f++) {
            u64 hd[4];
#pragma unroll
            for (int i = 0; i < 4; i++) hd[i] = pack_dup(hs[(rq * 4 + i) * 68 + f]);
            ulonglong2 wv = *(ulonglong2*)&W2c[f * 64 + dq * 4];
#pragma unroll
            for (int i = 0; i < 4; i++) {
                ffma2(acc2[i][0], hd[i], wv.x);
                ffma2(acc2[i][1], hd[i], wv.y);
            }
        }
    }

    float4 bb = *(float4*)&b2s[dq * 4];
#pragma unroll
    for (int i = 0; i < 4; i++) {
        float4 o; float x, y;
        unpack2(acc2[i][0], x, y); o.x = x + bb.x; o.y = y + bb.y;
        unpack2(acc2[i][1], x, y); o.z = x + bb.z; o.w = y + bb.w;
        *(float4*)&out[(size_t)(row0 + rq * 4 + i) * 64 + dq * 4] = o;
    }
}

// ---------------------------------------------------------------------------
static const int SMEM1 = (4096 + 128 * HPS) * 4;                               // 49,664 B
static const int SMEM2 = (1024 + 800 + 128 + 32 * TPS) * 8 + (4 * LSEQ + 4) * 4 + LSEQ * 4; // ~73.3 KB
static const int SMEM3 = (4096 + 4096 + 64 * 65 + 64 * 68 + 256 + 64) * 4;     // 68,096 B

extern "C" void kernel_launch(void* const* d_in, const int* in_sizes, int n_in,
                              void* d_out, int out_size) {
    const int*   his = (const int*)  d_in[0];
    const float* E   = (const float*)d_in[1];
    const float* S   = (const float*)d_in[2];
    const float* B0  = (const float*)d_in[3];
    const float* W1  = (const float*)d_in[4];
    const float* b1  = (const float*)d_in[5];
    const float* W2  = (const float*)d_in[6];
    const float* b2  = (const float*)d_in[7];
    float* out = (float*)d_out;

    cudaFuncSetAttribute(k_es,    cudaFuncAttributeMaxDynamicSharedMemorySize, SMEM1);
    cudaFuncSetAttribute(k_route, cudaFuncAttributeMaxDynamicSharedMemorySize, SMEM2);
    cudaFuncSetAttribute(k_mlp,   cudaFuncAttributeMaxDynamicSharedMemorySize, SMEM3);

    k_es<<<(VOCAB + 127) / 128, 256, SMEM1>>>(E, S);
    k_route<<<BS, 256, SMEM2>>>(his, B0);
    k_mlp<<<(BS * KCAPS) / 64, 256, SMEM3>>>(W1, b1, W2, b2, out);
}